// round 6
// baseline (speedup 1.0000x reference)
#include <cuda_runtime.h>
#include <cuda_fp16.h>

// Fan-beam CT forward projector.
// image [8,512,512] f32, views [360] f32 -> out [8,360,768] f32.
//
// R6: warp = 4 detectors x 8 sample-phases (compact ~3.5px-perp footprint;
// with dual layouts the slow-axis span averages ~5.6px vs ~7.3 for 8x4,
// cutting L1 wavefront replays). Clip box tightened so per-sample index
// clamps are provably redundant and removed. u8 image + pair packing +
// dp4a integer accumulation retained from R4.

namespace {
constexpr int IMG    = 512;
constexpr int PAD    = 2;
constexpr int PADN   = IMG + 2 * PAD;   // 516
constexpr int NB     = 8;
constexpr int NDET   = 768;
constexpr int NVIEWS = 360;
constexpr int NSAMP  = 768;

constexpr double PIX_D = 0.7433;
constexpr double DET_D = 1.2858;
constexpr double ISO_D = 595.0;
constexpr double SDD_D = 595.0 + 490.6;
constexpr double FOV_D = IMG * PIX_D * 0.70710678;
constexpr double T0_D  = ISO_D - FOV_D;
constexpr double DT_D  = 2.0 * FOV_D / NSAMP;

constexpr float DGAMMA  = (float)(DET_D / SDD_D);
constexpr float T0F     = (float)T0_D;
constexpr float DTF     = (float)DT_D;
constexpr float INV_PIX = (float)(1.0 / PIX_D);
constexpr float PI_F    = 3.14159265358979323846f;
}

// entry[u][v]: word k = b(2k)@v | b(2k)@(v+1)<<8 | b(2k+1)@v<<16 | b(2k+1)@(v+1)<<24
__device__ uint4 g_packA[PADN * PADN];   // slow=y, fast=x
__device__ uint4 g_packB[PADN * PADN];   // slow=x, fast=y

__device__ __forceinline__ void pix_u8(const float* __restrict__ img,
                                       int y, int x, unsigned v8[NB]) {
    const int BS = IMG * IMG;
    bool ok = (unsigned)y < (unsigned)IMG && (unsigned)x < (unsigned)IMG;
    int base = ok ? (y * IMG + x) : 0;
#pragma unroll
    for (int b = 0; b < NB; b++) {
        v8[b] = ok ? __float2uint_rn(img[b * BS + base] * 255.0f) : 0u;
    }
}

__device__ __forceinline__ uint4 pack_pair(const unsigned a[NB], const unsigned b[NB]) {
    uint4 u;
    u.x = a[0] | (b[0] << 8) | (a[1] << 16) | (b[1] << 24);
    u.y = a[2] | (b[2] << 8) | (a[3] << 16) | (b[3] << 24);
    u.z = a[4] | (b[4] << 8) | (a[5] << 16) | (b[5] << 24);
    u.w = a[6] | (b[6] << 8) | (a[7] << 16) | (b[7] << 24);
    return u;
}

__global__ void repack_kernel(const float* __restrict__ img) {
    int idx = blockIdx.x * blockDim.x + threadIdx.x;
    if (idx >= PADN * PADN) return;
    int pu = idx / PADN;
    int pv = idx - pu * PADN;
    int u = pu - PAD;
    int v = pv - PAD;

    unsigned p00[NB], pA1[NB], pB1[NB];
    pix_u8(img, u, v, p00);       // (y=u, x=v)
    pix_u8(img, u, v + 1, pA1);   // fast=x neighbor
    pix_u8(img, v + 1, u, pB1);   // layout B second pixel (y=v+1, x=u)

    g_packA[pu * PADN + pv] = pack_pair(p00, pA1);

    unsigned q0[NB];
    pix_u8(img, v, u, q0);        // (y=v, x=u)
    g_packB[pu * PADN + pv] = pack_pair(q0, pB1);
}

struct Sample {
    uint4 r0, r1;
    unsigned m0, m1, m2, m3;
};

__device__ __forceinline__ void sample_load(const uint4* __restrict__ pk,
                                            float fu, float fv, Sample& s) {
    float u0f = floorf(fu);
    float v0f = floorf(fv);
    float wu = fu - u0f;
    float wv = fv - v0f;
    int u0 = (int)u0f;   // guaranteed in [-2, 512] by the clip box
    int v0 = (int)v0f;
    const uint4* p = pk + (u0 + PAD) * PADN + (v0 + PAD);
    s.r0 = __ldg(p);
    s.r1 = __ldg(p + PADN);
    float wu1 = 1.0f - wu;
    float wv1 = 1.0f - wv;
    unsigned w00 = (unsigned)__float2int_rn(wu1 * wv1 * 255.0f);
    unsigned w01 = (unsigned)__float2int_rn(wu1 * wv * 255.0f);
    unsigned w10 = (unsigned)__float2int_rn(wu * wv1 * 255.0f);
    unsigned w11 = (unsigned)__float2int_rn(wu * wv * 255.0f);
    s.m0 = w00 | (w01 << 8);
    s.m1 = s.m0 << 16;
    s.m2 = w10 | (w11 << 8);
    s.m3 = s.m2 << 16;
}

__device__ __forceinline__ void sample_acc(const Sample& s, unsigned acc[NB]) {
    acc[0] = __dp4a(s.r0.x, s.m0, acc[0]);
    acc[1] = __dp4a(s.r0.x, s.m1, acc[1]);
    acc[2] = __dp4a(s.r0.y, s.m0, acc[2]);
    acc[3] = __dp4a(s.r0.y, s.m1, acc[3]);
    acc[4] = __dp4a(s.r0.z, s.m0, acc[4]);
    acc[5] = __dp4a(s.r0.z, s.m1, acc[5]);
    acc[6] = __dp4a(s.r0.w, s.m0, acc[6]);
    acc[7] = __dp4a(s.r0.w, s.m1, acc[7]);
    acc[0] = __dp4a(s.r1.x, s.m2, acc[0]);
    acc[1] = __dp4a(s.r1.x, s.m3, acc[1]);
    acc[2] = __dp4a(s.r1.y, s.m2, acc[2]);
    acc[3] = __dp4a(s.r1.y, s.m3, acc[3]);
    acc[4] = __dp4a(s.r1.z, s.m2, acc[4]);
    acc[5] = __dp4a(s.r1.z, s.m3, acc[5]);
    acc[6] = __dp4a(s.r1.w, s.m2, acc[6]);
    acc[7] = __dp4a(s.r1.w, s.m3, acc[7]);
}

// Block = 256 threads = 8 warps. Warp = 4 detectors x 8 sample phases.
// Block covers 32 detectors of one view.
__global__ __launch_bounds__(256) void proj_kernel(const float* __restrict__ views,
                                                   float* __restrict__ out) {
    const int lane = threadIdx.x & 31;
    const int warp = threadIdx.x >> 5;
    const int dsub = lane & 3;    // detector within warp (0..3)
    const int soff = lane >> 2;   // sample phase (0..7)

    const int d = blockIdx.x * 32 + warp * 4 + dsub;  // detector
    const int v = blockIdx.y;                          // view

    const float beta  = __ldg(&views[v]);
    const float gamma = ((float)d - (float)(NDET - 1) * 0.5f) * DGAMMA;

    float sb, cb;
    sincosf(beta, &sb, &cb);
    const float sx = (float)ISO_D * cb;
    const float sy = (float)ISO_D * sb;

    float diry, dirx;
    sincosf(beta + PI_F + gamma, &diry, &dirx);

    const float tstart = T0F + 0.5f * DTF;
    float bx = dirx * DTF * INV_PIX;
    float by = diry * DTF * INV_PIX;
    float ax = (sx + dirx * tstart) * INV_PIX + (float)(IMG - 1) * 0.5f;
    float ay = (sy + diry * tstart) * INV_PIX + (float)(IMG - 1) * 0.5f;

    // Clip sample range so every included sample has floor(f) in [-2, 512]:
    // box (-1.99, 512.99). Samples with f in (-2,-1] or [512,513) contribute
    // zero (padded image), so inclusion there is harmless; exclusion outside
    // is exact because all corners are out of support.
    float flo = 0.0f, fhi = (float)(NSAMP - 1);
    const float LOB = -1.99f, HIB = 512.99f;
    if (fabsf(bx) > 1e-7f) {
        float r  = 1.0f / bx;
        float t1 = (LOB - ax) * r;
        float t2 = (HIB - ax) * r;
        flo = fmaxf(flo, fminf(t1, t2));
        fhi = fminf(fhi, fmaxf(t1, t2));
    } else if (ax < LOB || ax > HIB) {
        fhi = -1.0f;
    }
    if (fabsf(by) > 1e-7f) {
        float r  = 1.0f / by;
        float t1 = (LOB - ay) * r;
        float t2 = (HIB - ay) * r;
        flo = fmaxf(flo, fminf(t1, t2));
        fhi = fminf(fhi, fmaxf(t1, t2));
    } else if (ay < LOB || ay > HIB) {
        fhi = -1.0f;
    }
    int i0 = max(0, (int)ceilf(flo));
    int i1 = min(NSAMP, (int)floorf(fhi) + 1);

    // Layout pick (warp-uniform): ray along x -> lanes spread along y -> layout B.
    bool wantB = fabsf(bx) >= fabsf(by);
    wantB = __shfl_sync(0xffffffffu, (int)wantB, 0) != 0;

    const uint4* __restrict__ pk;
    float au, bu, av, bv;  // u = slow axis, v = fast axis of chosen layout
    if (wantB) {
        pk = g_packB;       // slow=x, fast=y
        au = ax; bu = bx;
        av = ay; bv = by;
    } else {
        pk = g_packA;       // slow=y, fast=x
        au = ay; bu = by;
        av = ax; bv = bx;
    }

    unsigned acc[NB];
#pragma unroll
    for (int b = 0; b < NB; b++) acc[b] = 0u;

    // Lane handles samples i0+soff, i0+soff+8, ... Unroll x2 (stride 16).
    int i = i0 + soff;
    for (; i + 8 < i1; i += 16) {
        float f0 = (float)i;
        float f1 = (float)(i + 8);
        Sample s0, s1;
        sample_load(pk, fmaf(f0, bu, au), fmaf(f0, bv, av), s0);
        sample_load(pk, fmaf(f1, bu, au), fmaf(f1, bv, av), s1);
        sample_acc(s0, acc);
        sample_acc(s1, acc);
    }
    if (i < i1) {
        float f0 = (float)i;
        Sample s0;
        sample_load(pk, fmaf(f0, bu, au), fmaf(f0, bv, av), s0);
        sample_acc(s0, acc);
    }

    // Merge the 8 sample-phase partials (exact integer adds).
#pragma unroll
    for (int b = 0; b < NB; b++) {
        acc[b] += __shfl_xor_sync(0xffffffffu, acc[b], 4);
        acc[b] += __shfl_xor_sync(0xffffffffu, acc[b], 8);
        acc[b] += __shfl_xor_sync(0xffffffffu, acc[b], 16);
    }

    if (soff == 0) {
        const float scale = DTF / (255.0f * 255.0f);
#pragma unroll
        for (int b = 0; b < NB; b++) {
            out[(b * NVIEWS + v) * NDET + d] = (float)acc[b] * scale;
        }
    }
}

extern "C" void kernel_launch(void* const* d_in, const int* in_sizes, int n_in,
                              void* d_out, int out_size) {
    const float* image = (const float*)d_in[0];
    const float* views = (const float*)d_in[1];
    float* out = (float*)d_out;

    repack_kernel<<<(PADN * PADN + 255) / 256, 256>>>(image);
    proj_kernel<<<dim3(NDET / 32, NVIEWS), 256>>>(views, out);
}

// round 7
// speedup vs baseline: 1.4604x; 1.4604x over previous
#include <cuda_runtime.h>
#include <cuda_fp16.h>

// Fan-beam CT forward projector.
// image [8,512,512] f32, views [360] f32 -> out [8,360,768] f32.
//
// R7: slow-axis pair packing. entry[u][v] = 8 batches x pixels {(u,v),(u+1,v)}
// (u = slow axis). A bilinear sample reads entries [u0][v0] and [u0][v0+1] —
// ADJACENT 16B addresses, so both LDG.128s hit the same cache-line set
// (~9 wavefronts/sample vs 16 with fast-pair packing). Dual layouts + u8 +
// dp4a integer accumulation. Warp = 8 det x 4 sample phases (R4 geometry).

namespace {
constexpr int IMG    = 512;
constexpr int PAD    = 2;
constexpr int PADN   = IMG + 2 * PAD;   // 516
constexpr int NB     = 8;
constexpr int NDET   = 768;
constexpr int NVIEWS = 360;
constexpr int NSAMP  = 768;

constexpr double PIX_D = 0.7433;
constexpr double DET_D = 1.2858;
constexpr double ISO_D = 595.0;
constexpr double SDD_D = 595.0 + 490.6;
constexpr double FOV_D = IMG * PIX_D * 0.70710678;
constexpr double T0_D  = ISO_D - FOV_D;
constexpr double DT_D  = 2.0 * FOV_D / NSAMP;

constexpr float DGAMMA  = (float)(DET_D / SDD_D);
constexpr float T0F     = (float)T0_D;
constexpr float DTF     = (float)DT_D;
constexpr float INV_PIX = (float)(1.0 / PIX_D);
constexpr float PI_F    = 3.14159265358979323846f;
}

// entry[u][v], word k = b(2k)@(u,v) | b(2k)@(u+1,v)<<8 | b(2k+1)@(u,v)<<16 | b(2k+1)@(u+1,v)<<24
__device__ uint4 g_packA[PADN * PADN];   // slow=y, fast=x
__device__ uint4 g_packB[PADN * PADN];   // slow=x, fast=y

__device__ __forceinline__ void pix_u8(const float* __restrict__ img,
                                       int y, int x, unsigned v8[NB]) {
    const int BS = IMG * IMG;
    bool ok = (unsigned)y < (unsigned)IMG && (unsigned)x < (unsigned)IMG;
    int base = ok ? (y * IMG + x) : 0;
#pragma unroll
    for (int b = 0; b < NB; b++) {
        v8[b] = ok ? __float2uint_rn(img[b * BS + base] * 255.0f) : 0u;
    }
}

__device__ __forceinline__ uint4 pack_pair(const unsigned a[NB], const unsigned b[NB]) {
    uint4 u;
    u.x = a[0] | (b[0] << 8) | (a[1] << 16) | (b[1] << 24);
    u.y = a[2] | (b[2] << 8) | (a[3] << 16) | (b[3] << 24);
    u.z = a[4] | (b[4] << 8) | (a[5] << 16) | (b[5] << 24);
    u.w = a[6] | (b[6] << 8) | (a[7] << 16) | (b[7] << 24);
    return u;
}

__global__ void repack_kernel(const float* __restrict__ img) {
    int idx = blockIdx.x * blockDim.x + threadIdx.x;
    if (idx >= PADN * PADN) return;
    int pu = idx / PADN;
    int pv = idx - pu * PADN;
    int u = pu - PAD;
    int v = pv - PAD;

    // Layout A (slow=y, fast=x): pixels (y=u, x=v) and (y=u+1, x=v)
    unsigned a0[NB], a1[NB];
    pix_u8(img, u, v, a0);
    pix_u8(img, u + 1, v, a1);
    g_packA[pu * PADN + pv] = pack_pair(a0, a1);

    // Layout B (slow=x, fast=y): pixels (y=v, x=u) and (y=v, x=u+1)
    unsigned b0[NB], b1[NB];
    pix_u8(img, v, u, b0);
    pix_u8(img, v, u + 1, b1);
    g_packB[pu * PADN + pv] = pack_pair(b0, b1);
}

struct Sample {
    uint4 e0, e1;                 // entries (u0,v0) and (u0,v0+1)
    unsigned m0, m1, m2, m3;
};

__device__ __forceinline__ void sample_load(const uint4* __restrict__ pk,
                                            float fu, float fv, Sample& s) {
    float u0f = floorf(fu);
    float v0f = floorf(fv);
    float wu = fu - u0f;
    float wv = fv - v0f;
    int u0 = (int)u0f;   // guaranteed in [-2, 512] by the clip box
    int v0 = (int)v0f;
    const uint4* p = pk + (u0 + PAD) * PADN + (v0 + PAD);
    s.e0 = __ldg(p);
    s.e1 = __ldg(p + 1);
    float wu1 = 1.0f - wu;
    float wv1 = 1.0f - wv;
    // e0 bytes: {(u0,v0), (u0+1,v0)} -> weights {wu1*wv1, wu*wv1}
    // e1 bytes: {(u0,v0+1), (u0+1,v0+1)} -> weights {wu1*wv, wu*wv}
    unsigned w00 = (unsigned)__float2int_rn(wu1 * wv1 * 255.0f);
    unsigned w10 = (unsigned)__float2int_rn(wu * wv1 * 255.0f);
    unsigned w01 = (unsigned)__float2int_rn(wu1 * wv * 255.0f);
    unsigned w11 = (unsigned)__float2int_rn(wu * wv * 255.0f);
    s.m0 = w00 | (w10 << 8);
    s.m1 = s.m0 << 16;
    s.m2 = w01 | (w11 << 8);
    s.m3 = s.m2 << 16;
}

__device__ __forceinline__ void sample_acc(const Sample& s, unsigned acc[NB]) {
    acc[0] = __dp4a(s.e0.x, s.m0, acc[0]);
    acc[1] = __dp4a(s.e0.x, s.m1, acc[1]);
    acc[2] = __dp4a(s.e0.y, s.m0, acc[2]);
    acc[3] = __dp4a(s.e0.y, s.m1, acc[3]);
    acc[4] = __dp4a(s.e0.z, s.m0, acc[4]);
    acc[5] = __dp4a(s.e0.z, s.m1, acc[5]);
    acc[6] = __dp4a(s.e0.w, s.m0, acc[6]);
    acc[7] = __dp4a(s.e0.w, s.m1, acc[7]);
    acc[0] = __dp4a(s.e1.x, s.m2, acc[0]);
    acc[1] = __dp4a(s.e1.x, s.m3, acc[1]);
    acc[2] = __dp4a(s.e1.y, s.m2, acc[2]);
    acc[3] = __dp4a(s.e1.y, s.m3, acc[3]);
    acc[4] = __dp4a(s.e1.z, s.m2, acc[4]);
    acc[5] = __dp4a(s.e1.z, s.m3, acc[5]);
    acc[6] = __dp4a(s.e1.w, s.m2, acc[6]);
    acc[7] = __dp4a(s.e1.w, s.m3, acc[7]);
}

// Block = 128 threads = 4 warps. Warp = 8 detectors x 4 sample phases.
__global__ __launch_bounds__(128) void proj_kernel(const float* __restrict__ views,
                                                   float* __restrict__ out) {
    const int lane = threadIdx.x & 31;
    const int warp = threadIdx.x >> 5;
    const int dsub = lane & 7;    // detector within warp
    const int soff = lane >> 3;   // sample phase 0..3

    const int d = blockIdx.x * 32 + warp * 8 + dsub;  // detector
    const int v = blockIdx.y;                          // view

    const float beta  = __ldg(&views[v]);
    const float gamma = ((float)d - (float)(NDET - 1) * 0.5f) * DGAMMA;

    float sb, cb;
    sincosf(beta, &sb, &cb);
    const float sx = (float)ISO_D * cb;
    const float sy = (float)ISO_D * sb;

    float diry, dirx;
    sincosf(beta + PI_F + gamma, &diry, &dirx);

    const float tstart = T0F + 0.5f * DTF;
    float bx = dirx * DTF * INV_PIX;
    float by = diry * DTF * INV_PIX;
    float ax = (sx + dirx * tstart) * INV_PIX + (float)(IMG - 1) * 0.5f;
    float ay = (sy + diry * tstart) * INV_PIX + (float)(IMG - 1) * 0.5f;

    // Clip so every included sample has floor(f) in [-2, 512] on both axes.
    float flo = 0.0f, fhi = (float)(NSAMP - 1);
    const float LOB = -1.99f, HIB = 512.99f;
    if (fabsf(bx) > 1e-7f) {
        float r  = 1.0f / bx;
        float t1 = (LOB - ax) * r;
        float t2 = (HIB - ax) * r;
        flo = fmaxf(flo, fminf(t1, t2));
        fhi = fminf(fhi, fmaxf(t1, t2));
    } else if (ax < LOB || ax > HIB) {
        fhi = -1.0f;
    }
    if (fabsf(by) > 1e-7f) {
        float r  = 1.0f / by;
        float t1 = (LOB - ay) * r;
        float t2 = (HIB - ay) * r;
        flo = fmaxf(flo, fminf(t1, t2));
        fhi = fminf(fhi, fmaxf(t1, t2));
    } else if (ay < LOB || ay > HIB) {
        fhi = -1.0f;
    }
    int i0 = max(0, (int)ceilf(flo));
    int i1 = min(NSAMP, (int)floorf(fhi) + 1);

    // Layout pick (warp-uniform): ray along x -> lanes spread along y -> layout B.
    bool wantB = fabsf(bx) >= fabsf(by);
    wantB = __shfl_sync(0xffffffffu, (int)wantB, 0) != 0;

    const uint4* __restrict__ pk;
    float au, bu, av, bv;  // u = slow axis, v = fast axis of chosen layout
    if (wantB) {
        pk = g_packB;       // slow=x, fast=y
        au = ax; bu = bx;
        av = ay; bv = by;
    } else {
        pk = g_packA;       // slow=y, fast=x
        au = ay; bu = by;
        av = ax; bv = bx;
    }

    unsigned acc[NB];
#pragma unroll
    for (int b = 0; b < NB; b++) acc[b] = 0u;

    // Lane handles samples i0+soff, i0+soff+4, ... Unroll x2 (stride 8).
    int i = i0 + soff;
    for (; i + 4 < i1; i += 8) {
        float f0 = (float)i;
        float f1 = (float)(i + 4);
        Sample s0, s1;
        sample_load(pk, fmaf(f0, bu, au), fmaf(f0, bv, av), s0);
        sample_load(pk, fmaf(f1, bu, au), fmaf(f1, bv, av), s1);
        sample_acc(s0, acc);
        sample_acc(s1, acc);
    }
    if (i < i1) {
        float f0 = (float)i;
        Sample s0;
        sample_load(pk, fmaf(f0, bu, au), fmaf(f0, bv, av), s0);
        sample_acc(s0, acc);
    }

    // Merge the 4 sample-phase partials (exact integer adds).
#pragma unroll
    for (int b = 0; b < NB; b++) {
        acc[b] += __shfl_xor_sync(0xffffffffu, acc[b], 8);
        acc[b] += __shfl_xor_sync(0xffffffffu, acc[b], 16);
    }

    if (soff == 0) {
        const float scale = DTF / (255.0f * 255.0f);
#pragma unroll
        for (int b = 0; b < NB; b++) {
            out[(b * NVIEWS + v) * NDET + d] = (float)acc[b] * scale;
        }
    }
}

extern "C" void kernel_launch(void* const* d_in, const int* in_sizes, int n_in,
                              void* d_out, int out_size) {
    const float* image = (const float*)d_in[0];
    const float* views = (const float*)d_in[1];
    float* out = (float*)d_out;

    repack_kernel<<<(PADN * PADN + 255) / 256, 256>>>(image);
    proj_kernel<<<dim3(NDET / 32, NVIEWS), 128>>>(views, out);
}

// round 8
// speedup vs baseline: 1.4860x; 1.0176x over previous
#include <cuda_runtime.h>
#include <cuda_fp16.h>

// Fan-beam CT forward projector.
// image [8,512,512] f32, views [360] f32 -> out [8,360,768] f32.
//
// R8: 2D block-linear ("tiled") entry layout. One 128B cache line holds a
// 2(slow) x 4(fast) block of 16B entries, so the warp's tall-narrow gather
// footprint touches ~1.7x fewer lines per LDG than row-linear storage.
// Entries are slow-axis pairs (R7): entry[U][V] = 8 batches x {(u,v),(u+1,v)}.
// Dual layouts + u8 + dp4a integer accumulation. Warp = 8 det x 4 phases.

namespace {
constexpr int IMG    = 512;
constexpr int PAD    = 2;
constexpr int NB     = 8;
constexpr int NDET   = 768;
constexpr int NVIEWS = 360;
constexpr int NSAMP  = 768;

// Padded entry grid: U (slow) in [0, PADU), V (fast) in [0, PADV).
constexpr int PADU = 518;            // >= 516, even
constexpr int PADV = 520;            // >= 516, multiple of 4
constexpr int TV   = PADV / 4;       // tiles along fast = 130
constexpr int TU   = PADU / 2;       // tiles along slow = 259

constexpr double PIX_D = 0.7433;
constexpr double DET_D = 1.2858;
constexpr double ISO_D = 595.0;
constexpr double SDD_D = 595.0 + 490.6;
constexpr double FOV_D = IMG * PIX_D * 0.70710678;
constexpr double T0_D  = ISO_D - FOV_D;
constexpr double DT_D  = 2.0 * FOV_D / NSAMP;

constexpr float DGAMMA  = (float)(DET_D / SDD_D);
constexpr float T0F     = (float)T0_D;
constexpr float DTF     = (float)DT_D;
constexpr float INV_PIX = (float)(1.0 / PIX_D);
constexpr float PI_F    = 3.14159265358979323846f;
}

// Tiled storage: entry (U,V) lives at uint4 index
//   ((U>>1)*TV + (V>>2))*8 + (U&1)*4 + (V&3)
// i.e. tile = 128B = 2 rows x 4 entries. 259*130 tiles * 128B = 4.31 MB each.
__device__ uint4 g_packA[TU * TV * 8];   // slow=y, fast=x
__device__ uint4 g_packB[TU * TV * 8];   // slow=x, fast=y

__device__ __forceinline__ int tiled_idx(int U, int V) {
    return (((U >> 1) * TV + (V >> 2)) << 3) + ((U & 1) << 2) + (V & 3);
}

__device__ __forceinline__ void pix_u8(const float* __restrict__ img,
                                       int y, int x, unsigned v8[NB]) {
    const int BS = IMG * IMG;
    bool ok = (unsigned)y < (unsigned)IMG && (unsigned)x < (unsigned)IMG;
    int base = ok ? (y * IMG + x) : 0;
#pragma unroll
    for (int b = 0; b < NB; b++) {
        v8[b] = ok ? __float2uint_rn(img[b * BS + base] * 255.0f) : 0u;
    }
}

__device__ __forceinline__ uint4 pack_pair(const unsigned a[NB], const unsigned b[NB]) {
    uint4 u;
    u.x = a[0] | (b[0] << 8) | (a[1] << 16) | (b[1] << 24);
    u.y = a[2] | (b[2] << 8) | (a[3] << 16) | (b[3] << 24);
    u.z = a[4] | (b[4] << 8) | (a[5] << 16) | (b[5] << 24);
    u.w = a[6] | (b[6] << 8) | (a[7] << 16) | (b[7] << 24);
    return u;
}

__global__ void repack_kernel(const float* __restrict__ img) {
    int idx = blockIdx.x * blockDim.x + threadIdx.x;
    if (idx >= PADU * PADV) return;
    int U = idx / PADV;
    int V = idx - U * PADV;
    int u = U - PAD;
    int v = V - PAD;
    int ti = tiled_idx(U, V);

    // Layout A (slow=y, fast=x): pixels (y=u, x=v) and (y=u+1, x=v)
    unsigned a0[NB], a1[NB];
    pix_u8(img, u, v, a0);
    pix_u8(img, u + 1, v, a1);
    g_packA[ti] = pack_pair(a0, a1);

    // Layout B (slow=x, fast=y): pixels (y=v, x=u) and (y=v, x=u+1)
    unsigned b0[NB], b1[NB];
    pix_u8(img, v, u, b0);
    pix_u8(img, v, u + 1, b1);
    g_packB[ti] = pack_pair(b0, b1);
}

struct Sample {
    uint4 e0, e1;                 // entries (u0,v0) and (u0,v0+1)
    unsigned m0, m1, m2, m3;
};

__device__ __forceinline__ void sample_load(const uint4* __restrict__ pk,
                                            float fu, float fv, Sample& s) {
    float u0f = floorf(fu);
    float v0f = floorf(fv);
    float wu = fu - u0f;
    float wv = fv - v0f;
    int U = (int)u0f + PAD;   // in [0, 514] by the clip box
    int V = (int)v0f + PAD;
    s.e0 = __ldg(pk + tiled_idx(U, V));
    s.e1 = __ldg(pk + tiled_idx(U, V + 1));
    float wu1 = 1.0f - wu;
    float wv1 = 1.0f - wv;
    // e0 bytes: {(u0,v0), (u0+1,v0)}; e1 bytes: {(u0,v0+1), (u0+1,v0+1)}
    unsigned w00 = (unsigned)__float2int_rn(wu1 * wv1 * 255.0f);
    unsigned w10 = (unsigned)__float2int_rn(wu * wv1 * 255.0f);
    unsigned w01 = (unsigned)__float2int_rn(wu1 * wv * 255.0f);
    unsigned w11 = (unsigned)__float2int_rn(wu * wv * 255.0f);
    s.m0 = w00 | (w10 << 8);
    s.m1 = s.m0 << 16;
    s.m2 = w01 | (w11 << 8);
    s.m3 = s.m2 << 16;
}

__device__ __forceinline__ void sample_acc(const Sample& s, unsigned acc[NB]) {
    acc[0] = __dp4a(s.e0.x, s.m0, acc[0]);
    acc[1] = __dp4a(s.e0.x, s.m1, acc[1]);
    acc[2] = __dp4a(s.e0.y, s.m0, acc[2]);
    acc[3] = __dp4a(s.e0.y, s.m1, acc[3]);
    acc[4] = __dp4a(s.e0.z, s.m0, acc[4]);
    acc[5] = __dp4a(s.e0.z, s.m1, acc[5]);
    acc[6] = __dp4a(s.e0.w, s.m0, acc[6]);
    acc[7] = __dp4a(s.e0.w, s.m1, acc[7]);
    acc[0] = __dp4a(s.e1.x, s.m2, acc[0]);
    acc[1] = __dp4a(s.e1.x, s.m3, acc[1]);
    acc[2] = __dp4a(s.e1.y, s.m2, acc[2]);
    acc[3] = __dp4a(s.e1.y, s.m3, acc[3]);
    acc[4] = __dp4a(s.e1.z, s.m2, acc[4]);
    acc[5] = __dp4a(s.e1.z, s.m3, acc[5]);
    acc[6] = __dp4a(s.e1.w, s.m2, acc[6]);
    acc[7] = __dp4a(s.e1.w, s.m3, acc[7]);
}

// Block = 128 threads = 4 warps. Warp = 8 detectors x 4 sample phases.
__global__ __launch_bounds__(128) void proj_kernel(const float* __restrict__ views,
                                                   float* __restrict__ out) {
    const int lane = threadIdx.x & 31;
    const int warp = threadIdx.x >> 5;
    const int dsub = lane & 7;    // detector within warp
    const int soff = lane >> 3;   // sample phase 0..3

    const int d = blockIdx.x * 32 + warp * 8 + dsub;  // detector
    const int v = blockIdx.y;                          // view

    const float beta  = __ldg(&views[v]);
    const float gamma = ((float)d - (float)(NDET - 1) * 0.5f) * DGAMMA;

    float sb, cb;
    sincosf(beta, &sb, &cb);
    const float sx = (float)ISO_D * cb;
    const float sy = (float)ISO_D * sb;

    float diry, dirx;
    sincosf(beta + PI_F + gamma, &diry, &dirx);

    const float tstart = T0F + 0.5f * DTF;
    float bx = dirx * DTF * INV_PIX;
    float by = diry * DTF * INV_PIX;
    float ax = (sx + dirx * tstart) * INV_PIX + (float)(IMG - 1) * 0.5f;
    float ay = (sy + diry * tstart) * INV_PIX + (float)(IMG - 1) * 0.5f;

    // Clip so every included sample has floor(f) in [-2, 512] on both axes.
    float flo = 0.0f, fhi = (float)(NSAMP - 1);
    const float LOB = -1.99f, HIB = 512.99f;
    if (fabsf(bx) > 1e-7f) {
        float r  = 1.0f / bx;
        float t1 = (LOB - ax) * r;
        float t2 = (HIB - ax) * r;
        flo = fmaxf(flo, fminf(t1, t2));
        fhi = fminf(fhi, fmaxf(t1, t2));
    } else if (ax < LOB || ax > HIB) {
        fhi = -1.0f;
    }
    if (fabsf(by) > 1e-7f) {
        float r  = 1.0f / by;
        float t1 = (LOB - ay) * r;
        float t2 = (HIB - ay) * r;
        flo = fmaxf(flo, fminf(t1, t2));
        fhi = fminf(fhi, fmaxf(t1, t2));
    } else if (ay < LOB || ay > HIB) {
        fhi = -1.0f;
    }
    int i0 = max(0, (int)ceilf(flo));
    int i1 = min(NSAMP, (int)floorf(fhi) + 1);

    // Layout pick (warp-uniform).
    bool wantB = fabsf(bx) >= fabsf(by);
    wantB = __shfl_sync(0xffffffffu, (int)wantB, 0) != 0;

    const uint4* __restrict__ pk;
    float au, bu, av, bv;  // u = slow axis, v = fast axis of chosen layout
    if (wantB) {
        pk = g_packB;       // slow=x, fast=y
        au = ax; bu = bx;
        av = ay; bv = by;
    } else {
        pk = g_packA;       // slow=y, fast=x
        au = ay; bu = by;
        av = ax; bv = bx;
    }

    unsigned acc[NB];
#pragma unroll
    for (int b = 0; b < NB; b++) acc[b] = 0u;

    // Lane handles samples i0+soff, i0+soff+4, ... Unroll x2 (stride 8).
    int i = i0 + soff;
    for (; i + 4 < i1; i += 8) {
        float f0 = (float)i;
        float f1 = (float)(i + 4);
        Sample s0, s1;
        sample_load(pk, fmaf(f0, bu, au), fmaf(f0, bv, av), s0);
        sample_load(pk, fmaf(f1, bu, au), fmaf(f1, bv, av), s1);
        sample_acc(s0, acc);
        sample_acc(s1, acc);
    }
    if (i < i1) {
        float f0 = (float)i;
        Sample s0;
        sample_load(pk, fmaf(f0, bu, au), fmaf(f0, bv, av), s0);
        sample_acc(s0, acc);
    }

    // Merge the 4 sample-phase partials (exact integer adds).
#pragma unroll
    for (int b = 0; b < NB; b++) {
        acc[b] += __shfl_xor_sync(0xffffffffu, acc[b], 8);
        acc[b] += __shfl_xor_sync(0xffffffffu, acc[b], 16);
    }

    if (soff == 0) {
        const float scale = DTF / (255.0f * 255.0f);
#pragma unroll
        for (int b = 0; b < NB; b++) {
            out[(b * NVIEWS + v) * NDET + d] = (float)acc[b] * scale;
        }
    }
}

extern "C" void kernel_launch(void* const* d_in, const int* in_sizes, int n_in,
                              void* d_out, int out_size) {
    const float* image = (const float*)d_in[0];
    const float* views = (const float*)d_in[1];
    float* out = (float*)d_out;

    repack_kernel<<<(PADU * PADV + 255) / 256, 256>>>(image);
    proj_kernel<<<dim3(NDET / 32, NVIEWS), 128>>>(views, out);
}